// round 5
// baseline (speedup 1.0000x reference)
#include <cuda_runtime.h>
#include <stdint.h>

#define N_USERS 200000
#define N_ITEMS 100000
#define N_NODES 300000
#define N_EDGES 4800000
#define EMB 64
#define BATCH 4096
#define N_SEL 8192
#define CAP 128
#define NWORDS ((N_NODES + 31) / 32)   // 9375 words = 37.5KB

// Scratch (device globals; zero-initialized at module load)
__device__ unsigned g_bits[NWORDS];
__device__ int      g_slot[N_NODES];      // node -> slot+1, 0 = unset
__device__ int      g_cnt[N_SEL];
__device__ uint2    g_list[N_SEL * CAP];
__device__ int2     g_dup[N_SEL];
__device__ int      g_ndup;

// K1: clear exactly what this batch touches
__global__ void k_init(const int* __restrict__ user_id,
                       const int* __restrict__ item_id) {
    int i = blockIdx.x * blockDim.x + threadIdx.x;
    if (i >= N_SEL) return;
    int node = (i < BATCH) ? user_id[i] : N_USERS + item_id[i - BATCH];
    g_slot[node] = 0;
    atomicAnd(&g_bits[node >> 5], ~(1u << (node & 31)));
    g_cnt[i] = 0;
    if (i == 0) g_ndup = 0;
}

// K2: claim slots; record duplicate (loser, winner) pairs
__global__ void k_claim(const int* __restrict__ user_id,
                        const int* __restrict__ item_id) {
    int b = blockIdx.x * blockDim.x + threadIdx.x;
    if (b >= N_SEL) return;
    int node = (b < BATCH) ? user_id[b] : N_USERS + item_id[b - BATCH];
    atomicOr(&g_bits[node >> 5], 1u << (node & 31));
    int old = atomicCAS(&g_slot[node], 0, b + 1);
    if (old != 0) {
        int p = atomicAdd(&g_ndup, 1);
        g_dup[p] = make_int2(b, old - 1);
    }
}

// K3: edge scan with SHARED-MEMORY bitmap (kills L1 sector divergence).
// Grid-stride over int4 chunks; block loads the 37.5KB bitmap once.
#define SCAN_T 512
#define SCAN_B 296
__global__ void k_scan(const int*   __restrict__ adj_row,
                       const int*   __restrict__ adj_col,
                       const float* __restrict__ adj_vals) {
    __shared__ unsigned s_bits[NWORDS];
    for (int w = threadIdx.x; w < NWORDS; w += blockDim.x)
        s_bits[w] = g_bits[w];
    __syncthreads();

    const int4* row4 = (const int4*)adj_row;
    int nchunks = N_EDGES / 4;
    for (int i = blockIdx.x * blockDim.x + threadIdx.x; i < nchunks;
         i += gridDim.x * blockDim.x) {
        int4 r = row4[i];
        int e = i * 4;
#pragma unroll
        for (int k = 0; k < 4; k++) {
            int row = (k == 0) ? r.x : (k == 1) ? r.y : (k == 2) ? r.z : r.w;
            unsigned w = s_bits[row >> 5];              // LDS, ~4cyc conflicts
            if ((w >> (row & 31)) & 1u) {
                int s = g_slot[row] - 1;                // rare, L2 hit
                int pos = atomicAdd(&g_cnt[s], 1);
                if (pos < CAP)
                    g_list[s * CAP + pos] =
                        make_uint2((unsigned)adj_col[e + k],
                                   __float_as_uint(adj_vals[e + k]));
            }
        }
    }
}

// K4: TWO warps per slot; each warp owns a 128B half of the row
// (1 float per lane -> every edge gather is a single 128B line).
__global__ void k_acc(const int*   __restrict__ user_id,
                      const int*   __restrict__ item_id,
                      const float* __restrict__ user_emb,
                      const float* __restrict__ item_emb,
                      float*       __restrict__ out) {
    int g = blockIdx.x * (blockDim.x >> 5) + (threadIdx.x >> 5);
    int lane = threadIdx.x & 31;
    int s = g >> 1;
    int off = (g & 1) * 32 + lane;       // this warp's dim within the row
    if (s >= N_SEL) return;

    int node = (s < BATCH) ? user_id[s] : N_USERS + item_id[s - BATCH];
    const float* xp = (node < N_USERS)
        ? user_emb + (size_t)node * EMB
        : item_emb + (size_t)(node - N_USERS) * EMB;
    float a = 2.0f * xp[off];

    int n = g_cnt[s];
    if (n > CAP) n = CAP;

    for (int base = 0; base < n; base += 32) {
        uint2 ent = make_uint2(0u, 0u);
        if (base + lane < n) ent = g_list[s * CAP + base + lane];
        int m = n - base;
        if (m > 32) m = 32;

        int k = 0;
        for (; k + 4 <= m; k += 4) {     // unpredicated 4-edge groups
            float vv[4], rr[4];
#pragma unroll
            for (int j = 0; j < 4; j++) {
                int col = __shfl_sync(0xffffffffu, (int)ent.x, k + j);
                vv[j] = __uint_as_float(
                    __shfl_sync(0xffffffffu, ent.y, k + j));
                const float* cp = (col < N_USERS)
                    ? user_emb + (size_t)col * EMB
                    : item_emb + (size_t)(col - N_USERS) * EMB;
                rr[j] = cp[off];          // 4 independent 128B line loads
            }
#pragma unroll
            for (int j = 0; j < 4; j++)
                a = fmaf(vv[j], rr[j], a);
        }
        for (; k < m; k++) {
            int   col = __shfl_sync(0xffffffffu, (int)ent.x, k);
            float val = __uint_as_float(__shfl_sync(0xffffffffu, ent.y, k));
            const float* cp = (col < N_USERS)
                ? user_emb + (size_t)col * EMB
                : item_emb + (size_t)(col - N_USERS) * EMB;
            a = fmaf(val, cp[off], a);
        }
    }
    out[(size_t)s * EMB + off] = a;
}

// K5: duplicates copy the winner's finished output row
__global__ void k_dupfix(float* __restrict__ out) {
    int nd = g_ndup;
    int total = nd * (EMB / 4);
    float4* o4 = (float4*)out;
    for (int i = blockIdx.x * blockDim.x + threadIdx.x; i < total;
         i += gridDim.x * blockDim.x) {
        int2 d = g_dup[i >> 4];
        int  j = i & 15;
        o4[(size_t)d.x * 16 + j] = o4[(size_t)d.y * 16 + j];
    }
}

extern "C" void kernel_launch(void* const* d_in, const int* in_sizes, int n_in,
                              void* d_out, int out_size) {
    const float* user_emb = (const float*)d_in[0];
    const float* item_emb = (const float*)d_in[1];
    const int*   adj_row  = (const int*)d_in[2];
    const int*   adj_col  = (const int*)d_in[3];
    const float* adj_vals = (const float*)d_in[4];
    const int*   user_id  = (const int*)d_in[5];
    const int*   item_id  = (const int*)d_in[6];
    float*       out      = (float*)d_out;

    const int T = 256;
    k_init <<<(N_SEL + T - 1) / T, T>>>(user_id, item_id);
    k_claim<<<(N_SEL + T - 1) / T, T>>>(user_id, item_id);
    k_scan <<<SCAN_B, SCAN_T>>>(adj_row, adj_col, adj_vals);
    // 2 warps per slot -> 2*N_SEL warps, 8 warps per 256-thread block
    k_acc  <<<(2 * N_SEL) / (T / 32), T>>>(user_id, item_id,
                                           user_emb, item_emb, out);
    k_dupfix<<<32, T>>>(out);
}